// round 13
// baseline (speedup 1.0000x reference)
#include <cuda_runtime.h>

// Fixed shapes from reference setup_inputs
#define TT 4
#define BB 32
#define CC 256
#define HW 1024               // 32x32 plane
#define TB 128                // TT*BB
#define NSTAT 131072.0        // TB*HW
#define EPSV 1e-5
#define TSTRIDE (BB*CC*HW)    // element stride between timesteps

// Per-channel stat accumulators (double) + packed spike bits (4 MB).
// g_spk layout (producer K3 / consumer K4):
//   word = plane*32 + cg*4 + k   (plane=(t*BB+b)*CC+c, cg=col>>2, k=row>>3)
//   bit  = (row&7)*4 + j         (j = col&3)
__device__ double g_sum1[CC], g_sumsq1[CC], g_sum2[CC], g_sumsq2[CC];
__device__ unsigned g_spk[(TT * BB * CC * HW) / 32];

// Horizontal 3-tap conv on a float4 strip with scalar edge neighbors.
__device__ __forceinline__ float4 hconv(float w0, float w1, float w2,
                                        float l, float4 v, float r) {
    float4 o;
    o.x = fmaf(w0, l,   fmaf(w1, v.x, w2 * v.y));
    o.y = fmaf(w0, v.x, fmaf(w1, v.y, w2 * v.z));
    o.z = fmaf(w0, v.y, fmaf(w1, v.z, w2 * v.w));
    o.w = fmaf(w0, v.z, fmaf(w1, v.w, w2 * r));
    return o;
}

// ---------------------------------------------------------------------------
// K1: depthwise 3x3 conv + bias, per-channel sum/sumsq (BN1 stats).
// Warp = 4 planes, ASCENDING plane order (leaves the tail of x hot in L2 for
// K3's descending pass). 1024 blocks: 6.92 blk/SM -> 1.2% wave imbalance.
// Known-good ~29 us, at its FMA-pipe floor.
// ---------------------------------------------------------------------------
__global__ void __launch_bounds__(256) k_conv_stats(
    const float* __restrict__ x, const float* __restrict__ cw,
    const float* __restrict__ cb)
{
    const int lane = threadIdx.x & 31, warp = threadIdx.x >> 5;
    const int cg = lane & 7;                        // column group
    const int plane = blockIdx.x * 32 + warp * 4 + (lane >> 3);
    const int c = plane & (CC - 1);
    const float* xp = x + (size_t)plane * HW + cg * 4;

    if (blockIdx.x == 0) {  // zero BN2 stats (K1 never reads them)
        g_sum2[threadIdx.x] = 0.0; g_sumsq2[threadIdx.x] = 0.0;
    }

    float w[9];
    #pragma unroll
    for (int i = 0; i < 9; i++) w[i] = __ldg(&cw[c * 9 + i]);
    const float bias = __ldg(&cb[c]);

    float4 acc0 = {0,0,0,0}, acc1 = {0,0,0,0};
    float s = 0.f, ss = 0.f;

    #pragma unroll 8
    for (int r = 0; r < 32; r++) {
        const float4 v = __ldg(reinterpret_cast<const float4*>(xp + r * 32));
        float hl = __shfl_up_sync(0xffffffffu, v.w, 1);   if (cg == 0) hl = 0.f;
        float hr = __shfl_down_sync(0xffffffffu, v.x, 1); if (cg == 7) hr = 0.f;
        float4 a = hconv(w[0], w[1], w[2], hl, v, hr);
        float4 m = hconv(w[3], w[4], w[5], hl, v, hr);
        float4 d = hconv(w[6], w[7], w[8], hl, v, hr);
        if (r) {  // output row r-1 complete
            float yx = acc0.x + d.x + bias, yy = acc0.y + d.y + bias;
            float yz = acc0.z + d.z + bias, yw = acc0.w + d.w + bias;
            s += (yx + yy) + (yz + yw);
            ss = fmaf(yx, yx, fmaf(yy, yy, fmaf(yz, yz, fmaf(yw, yw, ss))));
        }
        acc0.x = acc1.x + m.x; acc0.y = acc1.y + m.y;
        acc0.z = acc1.z + m.z; acc0.w = acc1.w + m.w;
        acc1 = a;
    }
    {   // output row 31 (bottom halo = 0)
        float yx = acc0.x + bias, yy = acc0.y + bias;
        float yz = acc0.z + bias, yw = acc0.w + bias;
        s += (yx + yy) + (yz + yw);
        ss = fmaf(yx, yx, fmaf(yy, yy, fmaf(yz, yz, fmaf(yw, yw, ss))));
    }
    #pragma unroll
    for (int o = 4; o > 0; o >>= 1) {  // reduce within 8-lane plane group
        s  += __shfl_xor_sync(0xffffffffu, s, o);
        ss += __shfl_xor_sync(0xffffffffu, ss, o);
    }
    if (cg == 0) {
        atomicAdd(&g_sum1[c], (double)s);
        atomicAdd(&g_sumsq1[c], (double)ss);
    }
}

// ---------------------------------------------------------------------------
// K3: fused conv+LIF, warp = 4 planes, 1-row prefetch, DESCENDING plane order
// (L2 chaining with K1). NOW 64-THREAD BLOCKS / 1024 BLOCKS: 6.92 blk/SM ->
// wave imbalance drops from 16% (512 blk @ 3.46/SM) to 1.2%. No __syncthreads
// and all reductions are warp-local, so semantics are unchanged.
// ---------------------------------------------------------------------------
__global__ void __launch_bounds__(64) k_lif(
    const float* __restrict__ x, const float* __restrict__ cw,
    const float* __restrict__ cb, const float* __restrict__ g1,
    const float* __restrict__ b1)
{
    const int lane = threadIdx.x & 31, warp = threadIdx.x >> 5;
    const int cg = lane & 7;
    const int rbid = (int)gridDim.x - 1 - (int)blockIdx.x;      // reversed
    const int plane = (rbid * 2 + warp) * 4 + (lane >> 3);      // b*CC + c
    const int c = plane & (CC - 1);
    const float* xp = x + (size_t)plane * HW + cg * 4;

    float w[9];
    #pragma unroll
    for (int i = 0; i < 9; i++) w[i] = __ldg(&cw[c * 9 + i]);

    const double mu  = g_sum1[c] * (1.0 / NSTAT);
    const double var = g_sumsq1[c] * (1.0 / NSTAT) - mu * mu;
    const float scale1 = __ldg(&g1[c]) * (float)rsqrt(var + EPSV);
    const float shift1 = __ldg(&b1[c]) + (__ldg(&cb[c]) - (float)mu) * scale1;

    float4 acc0[TT], acc1[TT], vprev[TT], vbuf[TT];
    unsigned spw[TT];
    #pragma unroll
    for (int t = 0; t < TT; t++) {
        acc0[t] = make_float4(0,0,0,0); acc1[t] = make_float4(0,0,0,0);
        vprev[t] = make_float4(0,0,0,0); spw[t] = 0u;
        vbuf[t] = __ldg(reinterpret_cast<const float4*>(
                        xp + (size_t)t * TSTRIDE));   // preload row 0
    }
    float s2 = 0.f, ss2 = 0.f;

    #pragma unroll 2
    for (int r = 0; r < 32; r++) {
        // ---- prefetch row r+1 first (row 31 reloads itself: L1 hit) ----
        float4 vnext[TT];
        const int rn = (r < 31) ? r + 1 : 31;
        #pragma unroll
        for (int t = 0; t < TT; t++)
            vnext[t] = __ldg(reinterpret_cast<const float4*>(
                             xp + (size_t)t * TSTRIDE + rn * 32));

        const bool out_valid = (r >= 1);
        const int sh = ((r - 1) & 7) * 4;        // nibble shift for output row
        float4 vm = make_float4(0,0,0,0);        // membrane, chains over t
        #pragma unroll
        for (int t = 0; t < TT; t++) {
            const float4 v = vbuf[t];
            float hl = __shfl_up_sync(0xffffffffu, v.w, 1);   if (cg == 0) hl = 0.f;
            float hr = __shfl_down_sync(0xffffffffu, v.x, 1); if (cg == 7) hr = 0.f;
            float4 a = hconv(w[0], w[1], w[2], hl, v, hr);
            float4 m = hconv(w[3], w[4], w[5], hl, v, hr);
            float4 d = hconv(w[6], w[7], w[8], hl, v, hr);
            if (out_valid) {   // output row r-1 for timestep t
                float yx = fmaf(acc0[t].x + d.x, scale1, shift1);
                float yy = fmaf(acc0[t].y + d.y, scale1, shift1);
                float yz = fmaf(acc0[t].z + d.z, scale1, shift1);
                float yw = fmaf(acc0[t].w + d.w, scale1, shift1);
                float hx = fmaf(yx - vm.x, 0.5f, vm.x);
                float hy = fmaf(yy - vm.y, 0.5f, vm.y);
                float hz = fmaf(yz - vm.z, 0.5f, vm.z);
                float hw = fmaf(yw - vm.w, 0.5f, vm.w);
                bool f0 = hx >= 1.f, f1 = hy >= 1.f, f2 = hz >= 1.f, f3 = hw >= 1.f;
                vm.x = f0 ? 0.f : hx; vm.y = f1 ? 0.f : hy;
                vm.z = f2 ? 0.f : hz; vm.w = f3 ? 0.f : hw;
                unsigned nib = (f0 ? 1u : 0u) | (f1 ? 2u : 0u)
                             | (f2 ? 4u : 0u) | (f3 ? 8u : 0u);
                spw[t] |= nib << sh;
                float zx = (f0 ? 1.f : 0.f) + vprev[t].x;
                float zy = (f1 ? 1.f : 0.f) + vprev[t].y;
                float zz = (f2 ? 1.f : 0.f) + vprev[t].z;
                float zw = (f3 ? 1.f : 0.f) + vprev[t].w;
                s2 += (zx + zy) + (zz + zw);
                ss2 = fmaf(zx, zx, fmaf(zy, zy, fmaf(zz, zz, fmaf(zw, zw, ss2))));
            }
            acc0[t].x = acc1[t].x + m.x; acc0[t].y = acc1[t].y + m.y;
            acc0[t].z = acc1[t].z + m.z; acc0[t].w = acc1[t].w + m.w;
            acc1[t] = a;
            vprev[t] = v;
            vbuf[t] = vnext[t];
        }
        if (out_valid && (((r - 1) & 7) == 7)) {  // flush rows (r-1 = 7,15,23)
            const int k = (r - 1) >> 3;
            #pragma unroll
            for (int t = 0; t < TT; t++) {
                g_spk[((size_t)(t * BB * CC) + plane) * 32 + cg * 4 + k] = spw[t];
                spw[t] = 0u;
            }
        }
    }
    {   // output row 31 (conv = acc0; bottom halo = 0); vprev = x row 31
        float4 vm = make_float4(0,0,0,0);
        #pragma unroll
        for (int t = 0; t < TT; t++) {
            float yx = fmaf(acc0[t].x, scale1, shift1);
            float yy = fmaf(acc0[t].y, scale1, shift1);
            float yz = fmaf(acc0[t].z, scale1, shift1);
            float yw = fmaf(acc0[t].w, scale1, shift1);
            float hx = fmaf(yx - vm.x, 0.5f, vm.x);
            float hy = fmaf(yy - vm.y, 0.5f, vm.y);
            float hz = fmaf(yz - vm.z, 0.5f, vm.z);
            float hw = fmaf(yw - vm.w, 0.5f, vm.w);
            bool f0 = hx >= 1.f, f1 = hy >= 1.f, f2 = hz >= 1.f, f3 = hw >= 1.f;
            vm.x = f0 ? 0.f : hx; vm.y = f1 ? 0.f : hy;
            vm.z = f2 ? 0.f : hz; vm.w = f3 ? 0.f : hw;
            unsigned nib = (f0 ? 1u : 0u) | (f1 ? 2u : 0u)
                         | (f2 ? 4u : 0u) | (f3 ? 8u : 0u);
            spw[t] |= nib << 28;  // (31&7)*4
            float zx = (f0 ? 1.f : 0.f) + vprev[t].x;
            float zy = (f1 ? 1.f : 0.f) + vprev[t].y;
            float zz = (f2 ? 1.f : 0.f) + vprev[t].z;
            float zw = (f3 ? 1.f : 0.f) + vprev[t].w;
            s2 += (zx + zy) + (zz + zw);
            ss2 = fmaf(zx, zx, fmaf(zy, zy, fmaf(zz, zz, fmaf(zw, zw, ss2))));
            g_spk[((size_t)(t * BB * CC) + plane) * 32 + cg * 4 + 3] = spw[t];
        }
    }
    #pragma unroll
    for (int o = 4; o > 0; o >>= 1) {  // reduce within 8-lane plane group
        s2  += __shfl_xor_sync(0xffffffffu, s2, o);
        ss2 += __shfl_xor_sync(0xffffffffu, ss2, o);
    }
    if (cg == 0) {
        atomicAdd(&g_sum2[c], (double)s2);
        atomicAdd(&g_sumsq2[c], (double)ss2);
    }
}

// ---------------------------------------------------------------------------
// K4: out = BN2(spike + x), ascending order (picks up K3-descending's L2 tail).
// One block = one (t,b,c) plane; params once/block. Block 0 zeros BN1 stats.
// ---------------------------------------------------------------------------
__global__ void __launch_bounds__(256) k_bn2(
    const float* __restrict__ x, const float* __restrict__ g2,
    const float* __restrict__ b2, float* __restrict__ out)
{
    __shared__ float s_scale, s_shift;
    const int c = blockIdx.x & (CC - 1);

    if (threadIdx.x == 0) {
        double m   = g_sum2[c] * (1.0 / NSTAT);
        double var = g_sumsq2[c] * (1.0 / NSTAT) - m * m;
        float  sc  = __ldg(&g2[c]) * (float)rsqrt(var + EPSV);
        s_scale = sc;
        s_shift = __ldg(&b2[c]) - (float)m * sc;
    }
    if (blockIdx.x == 0) {  // reset BN1 stats for next launch
        g_sum1[threadIdx.x] = 0.0; g_sumsq1[threadIdx.x] = 0.0;
    }
    __syncthreads();
    const float scale2 = s_scale, shift2 = s_shift;

    const unsigned i4 = blockIdx.x * 256u + threadIdx.x;  // float4 index
    const float4 xv = reinterpret_cast<const float4*>(x)[i4];

    // word = plane*32 + cg*4 + k ; plane=i4>>8, cg=i4&7, k=(i4>>6)&3
    const unsigned widx = (i4 >> 8) * 32u + (i4 & 7u) * 4u + ((i4 >> 6) & 3u);
    const unsigned wbits = g_spk[widx];
    const int sh = (int)((i4 >> 1) & 0x1Cu);  // ((row&7)*4)

    float4 o;
    o.x = (xv.x + (float)((wbits >> (sh + 0)) & 1u)) * scale2 + shift2;
    o.y = (xv.y + (float)((wbits >> (sh + 1)) & 1u)) * scale2 + shift2;
    o.z = (xv.z + (float)((wbits >> (sh + 2)) & 1u)) * scale2 + shift2;
    o.w = (xv.w + (float)((wbits >> (sh + 3)) & 1u)) * scale2 + shift2;
    reinterpret_cast<float4*>(out)[i4] = o;
}

// ---------------------------------------------------------------------------
extern "C" void kernel_launch(void* const* d_in, const int* in_sizes, int n_in,
                              void* d_out, int out_size) {
    const float* x  = (const float*)d_in[0];
    const float* cw = (const float*)d_in[1];
    const float* cb = (const float*)d_in[2];
    const float* g1 = (const float*)d_in[3];
    const float* b1 = (const float*)d_in[4];
    const float* g2 = (const float*)d_in[5];
    const float* b2 = (const float*)d_in[6];
    float* out = (float*)d_out;

    k_conv_stats<<<(TB * CC) / 32, 256>>>(x, cw, cb);    // 1024 blocks, asc
    k_lif<<<(BB * CC) / 8, 64>>>(x, cw, cb, g1, b1);     // 1024 blocks, DESC
    k_bn2<<<TB * CC, 256>>>(x, g2, b2, out);             // 32768 blocks, asc
}

// round 14
// speedup vs baseline: 1.0195x; 1.0195x over previous
#include <cuda_runtime.h>

// Fixed shapes from reference setup_inputs
#define TT 4
#define BB 32
#define CC 256
#define HW 1024               // 32x32 plane
#define TB 128                // TT*BB
#define NSTAT 131072.0        // TB*HW
#define EPSV 1e-5
#define TSTRIDE (BB*CC*HW)    // element stride between timesteps

// Per-channel stat accumulators (double) + packed spike bits (4 MB).
// g_spk layout (producer K3 / consumer K4):
//   word = plane*32 + cg*4 + k   (plane=(t*BB+b)*CC+c, cg=col>>2, k=row>>3)
//   bit  = (row&7)*4 + j         (j = col&3)
__device__ double g_sum1[CC], g_sumsq1[CC], g_sum2[CC], g_sumsq2[CC];
__device__ unsigned g_spk[(TT * BB * CC * HW) / 32];

// Horizontal 3-tap conv on a float4 strip with scalar edge neighbors.
__device__ __forceinline__ float4 hconv(float w0, float w1, float w2,
                                        float l, float4 v, float r) {
    float4 o;
    o.x = fmaf(w0, l,   fmaf(w1, v.x, w2 * v.y));
    o.y = fmaf(w0, v.x, fmaf(w1, v.y, w2 * v.z));
    o.z = fmaf(w0, v.y, fmaf(w1, v.z, w2 * v.w));
    o.w = fmaf(w0, v.z, fmaf(w1, v.w, w2 * r));
    return o;
}

// ---------------------------------------------------------------------------
// K1: depthwise 3x3 conv + bias, per-channel sum/sumsq (BN1 stats).
// Warp = 4 planes, ASCENDING plane order (leaves the tail of x hot in L2 for
// K3's descending pass). Known-good ~29 us, at its FMA-pipe floor.
// ---------------------------------------------------------------------------
__global__ void __launch_bounds__(256) k_conv_stats(
    const float* __restrict__ x, const float* __restrict__ cw,
    const float* __restrict__ cb)
{
    const int lane = threadIdx.x & 31, warp = threadIdx.x >> 5;
    const int cg = lane & 7;                        // column group
    const int plane = blockIdx.x * 32 + warp * 4 + (lane >> 3);
    const int c = plane & (CC - 1);
    const float* xp = x + (size_t)plane * HW + cg * 4;

    if (blockIdx.x == 0) {  // zero BN2 stats (K1 never reads them)
        g_sum2[threadIdx.x] = 0.0; g_sumsq2[threadIdx.x] = 0.0;
    }

    float w[9];
    #pragma unroll
    for (int i = 0; i < 9; i++) w[i] = __ldg(&cw[c * 9 + i]);
    const float bias = __ldg(&cb[c]);

    float4 acc0 = {0,0,0,0}, acc1 = {0,0,0,0};
    float s = 0.f, ss = 0.f;

    #pragma unroll 8
    for (int r = 0; r < 32; r++) {
        const float4 v = __ldg(reinterpret_cast<const float4*>(xp + r * 32));
        float hl = __shfl_up_sync(0xffffffffu, v.w, 1);   if (cg == 0) hl = 0.f;
        float hr = __shfl_down_sync(0xffffffffu, v.x, 1); if (cg == 7) hr = 0.f;
        float4 a = hconv(w[0], w[1], w[2], hl, v, hr);
        float4 m = hconv(w[3], w[4], w[5], hl, v, hr);
        float4 d = hconv(w[6], w[7], w[8], hl, v, hr);
        if (r) {  // output row r-1 complete
            float yx = acc0.x + d.x + bias, yy = acc0.y + d.y + bias;
            float yz = acc0.z + d.z + bias, yw = acc0.w + d.w + bias;
            s += (yx + yy) + (yz + yw);
            ss = fmaf(yx, yx, fmaf(yy, yy, fmaf(yz, yz, fmaf(yw, yw, ss))));
        }
        acc0.x = acc1.x + m.x; acc0.y = acc1.y + m.y;
        acc0.z = acc1.z + m.z; acc0.w = acc1.w + m.w;
        acc1 = a;
    }
    {   // output row 31 (bottom halo = 0)
        float yx = acc0.x + bias, yy = acc0.y + bias;
        float yz = acc0.z + bias, yw = acc0.w + bias;
        s += (yx + yy) + (yz + yw);
        ss = fmaf(yx, yx, fmaf(yy, yy, fmaf(yz, yz, fmaf(yw, yw, ss))));
    }
    #pragma unroll
    for (int o = 4; o > 0; o >>= 1) {  // reduce within 8-lane plane group
        s  += __shfl_xor_sync(0xffffffffu, s, o);
        ss += __shfl_xor_sync(0xffffffffu, ss, o);
    }
    if (cg == 0) {
        atomicAdd(&g_sum1[c], (double)s);
        atomicAdd(&g_sumsq1[c], (double)ss);
    }
}

// ---------------------------------------------------------------------------
// K3: fused conv+LIF, warp = 4 planes, 1-row prefetch, DESCENDING plane order
// (L2 chaining with K1). R12 structure (128-thr blocks, best measured), plus
// BN1 FOLDING: 0.5*scale1 into conv weights, 0.5*shift1 into shift_h, so
//   h = fmaf(vm, 0.5, conv' + shift_h)   — one fewer FMA per px per t.
// ---------------------------------------------------------------------------
__global__ void __launch_bounds__(128) k_lif(
    const float* __restrict__ x, const float* __restrict__ cw,
    const float* __restrict__ cb, const float* __restrict__ g1,
    const float* __restrict__ b1)
{
    const int lane = threadIdx.x & 31, warp = threadIdx.x >> 5;
    const int cg = lane & 7;
    const int rbid = (int)gridDim.x - 1 - (int)blockIdx.x;      // reversed
    const int plane = rbid * 16 + warp * 4 + (lane >> 3);       // b*CC + c
    const int c = plane & (CC - 1);
    const float* xp = x + (size_t)plane * HW + cg * 4;

    const double mu  = g_sum1[c] * (1.0 / NSTAT);
    const double var = g_sumsq1[c] * (1.0 / NSTAT) - mu * mu;
    const float scale1 = __ldg(&g1[c]) * (float)rsqrt(var + EPSV);
    const float shift_h = 0.5f * (__ldg(&b1[c]) + (__ldg(&cb[c]) - (float)mu) * scale1);
    const float ws = 0.5f * scale1;
    float w[9];
    #pragma unroll
    for (int i = 0; i < 9; i++) w[i] = __ldg(&cw[c * 9 + i]) * ws;

    float4 acc0[TT], acc1[TT], vprev[TT], vbuf[TT];
    unsigned spw[TT];
    #pragma unroll
    for (int t = 0; t < TT; t++) {
        acc0[t] = make_float4(0,0,0,0); acc1[t] = make_float4(0,0,0,0);
        vprev[t] = make_float4(0,0,0,0); spw[t] = 0u;
        vbuf[t] = __ldg(reinterpret_cast<const float4*>(
                        xp + (size_t)t * TSTRIDE));   // preload row 0
    }
    float s2 = 0.f, ss2 = 0.f;

    #pragma unroll 2
    for (int r = 0; r < 32; r++) {
        // ---- prefetch row r+1 first (row 31 reloads itself: L1 hit) ----
        float4 vnext[TT];
        const int rn = (r < 31) ? r + 1 : 31;
        #pragma unroll
        for (int t = 0; t < TT; t++)
            vnext[t] = __ldg(reinterpret_cast<const float4*>(
                             xp + (size_t)t * TSTRIDE + rn * 32));

        const bool out_valid = (r >= 1);
        const int sh = ((r - 1) & 7) * 4;        // nibble shift for output row
        float4 vm = make_float4(0,0,0,0);        // membrane, chains over t
        #pragma unroll
        for (int t = 0; t < TT; t++) {
            const float4 v = vbuf[t];
            float hl = __shfl_up_sync(0xffffffffu, v.w, 1);   if (cg == 0) hl = 0.f;
            float hr = __shfl_down_sync(0xffffffffu, v.x, 1); if (cg == 7) hr = 0.f;
            float4 a = hconv(w[0], w[1], w[2], hl, v, hr);
            float4 m = hconv(w[3], w[4], w[5], hl, v, hr);
            float4 d = hconv(w[6], w[7], w[8], hl, v, hr);
            if (out_valid) {   // output row r-1 for timestep t
                float hx = fmaf(vm.x, 0.5f, acc0[t].x + d.x + shift_h);
                float hy = fmaf(vm.y, 0.5f, acc0[t].y + d.y + shift_h);
                float hz = fmaf(vm.z, 0.5f, acc0[t].z + d.z + shift_h);
                float hw = fmaf(vm.w, 0.5f, acc0[t].w + d.w + shift_h);
                bool f0 = hx >= 1.f, f1 = hy >= 1.f, f2 = hz >= 1.f, f3 = hw >= 1.f;
                vm.x = f0 ? 0.f : hx; vm.y = f1 ? 0.f : hy;
                vm.z = f2 ? 0.f : hz; vm.w = f3 ? 0.f : hw;
                unsigned nib = (f0 ? 1u : 0u) | (f1 ? 2u : 0u)
                             | (f2 ? 4u : 0u) | (f3 ? 8u : 0u);
                spw[t] |= nib << sh;
                float zx = (f0 ? 1.f : 0.f) + vprev[t].x;
                float zy = (f1 ? 1.f : 0.f) + vprev[t].y;
                float zz = (f2 ? 1.f : 0.f) + vprev[t].z;
                float zw = (f3 ? 1.f : 0.f) + vprev[t].w;
                s2 += (zx + zy) + (zz + zw);
                ss2 = fmaf(zx, zx, fmaf(zy, zy, fmaf(zz, zz, fmaf(zw, zw, ss2))));
            }
            acc0[t].x = acc1[t].x + m.x; acc0[t].y = acc1[t].y + m.y;
            acc0[t].z = acc1[t].z + m.z; acc0[t].w = acc1[t].w + m.w;
            acc1[t] = a;
            vprev[t] = v;
            vbuf[t] = vnext[t];
        }
        if (out_valid && (((r - 1) & 7) == 7)) {  // flush rows (r-1 = 7,15,23)
            const int k = (r - 1) >> 3;
            #pragma unroll
            for (int t = 0; t < TT; t++) {
                g_spk[((size_t)(t * BB * CC) + plane) * 32 + cg * 4 + k] = spw[t];
                spw[t] = 0u;
            }
        }
    }
    {   // output row 31 (conv' = acc0; bottom halo = 0); vprev = x row 31
        float4 vm = make_float4(0,0,0,0);
        #pragma unroll
        for (int t = 0; t < TT; t++) {
            float hx = fmaf(vm.x, 0.5f, acc0[t].x + shift_h);
            float hy = fmaf(vm.y, 0.5f, acc0[t].y + shift_h);
            float hz = fmaf(vm.z, 0.5f, acc0[t].z + shift_h);
            float hw = fmaf(vm.w, 0.5f, acc0[t].w + shift_h);
            bool f0 = hx >= 1.f, f1 = hy >= 1.f, f2 = hz >= 1.f, f3 = hw >= 1.f;
            vm.x = f0 ? 0.f : hx; vm.y = f1 ? 0.f : hy;
            vm.z = f2 ? 0.f : hz; vm.w = f3 ? 0.f : hw;
            unsigned nib = (f0 ? 1u : 0u) | (f1 ? 2u : 0u)
                         | (f2 ? 4u : 0u) | (f3 ? 8u : 0u);
            spw[t] |= nib << 28;  // (31&7)*4
            float zx = (f0 ? 1.f : 0.f) + vprev[t].x;
            float zy = (f1 ? 1.f : 0.f) + vprev[t].y;
            float zz = (f2 ? 1.f : 0.f) + vprev[t].z;
            float zw = (f3 ? 1.f : 0.f) + vprev[t].w;
            s2 += (zx + zy) + (zz + zw);
            ss2 = fmaf(zx, zx, fmaf(zy, zy, fmaf(zz, zz, fmaf(zw, zw, ss2))));
            g_spk[((size_t)(t * BB * CC) + plane) * 32 + cg * 4 + 3] = spw[t];
        }
    }
    #pragma unroll
    for (int o = 4; o > 0; o >>= 1) {  // reduce within 8-lane plane group
        s2  += __shfl_xor_sync(0xffffffffu, s2, o);
        ss2 += __shfl_xor_sync(0xffffffffu, ss2, o);
    }
    if (cg == 0) {
        atomicAdd(&g_sum2[c], (double)s2);
        atomicAdd(&g_sumsq2[c], (double)ss2);
    }
}

// ---------------------------------------------------------------------------
// K4: out = BN2(spike + x), ascending order (picks up K3-descending's L2 tail).
// Streaming stores (__stcs) keep x's L2 lines resident. One block = one plane.
// Block 0 zeros BN1 stats for the next launch.
// ---------------------------------------------------------------------------
__global__ void __launch_bounds__(256) k_bn2(
    const float* __restrict__ x, const float* __restrict__ g2,
    const float* __restrict__ b2, float* __restrict__ out)
{
    __shared__ float s_scale, s_shift;
    const int c = blockIdx.x & (CC - 1);

    if (threadIdx.x == 0) {
        double m   = g_sum2[c] * (1.0 / NSTAT);
        double var = g_sumsq2[c] * (1.0 / NSTAT) - m * m;
        float  sc  = __ldg(&g2[c]) * (float)rsqrt(var + EPSV);
        s_scale = sc;
        s_shift = __ldg(&b2[c]) - (float)m * sc;
    }
    if (blockIdx.x == 0) {  // reset BN1 stats for next launch
        g_sum1[threadIdx.x] = 0.0; g_sumsq1[threadIdx.x] = 0.0;
    }
    __syncthreads();
    const float scale2 = s_scale, shift2 = s_shift;

    const unsigned i4 = blockIdx.x * 256u + threadIdx.x;  // float4 index
    const float4 xv = reinterpret_cast<const float4*>(x)[i4];

    // word = plane*32 + cg*4 + k ; plane=i4>>8, cg=i4&7, k=(i4>>6)&3
    const unsigned widx = (i4 >> 8) * 32u + (i4 & 7u) * 4u + ((i4 >> 6) & 3u);
    const unsigned wbits = g_spk[widx];
    const int sh = (int)((i4 >> 1) & 0x1Cu);  // ((row&7)*4)

    float4 o;
    o.x = (xv.x + (float)((wbits >> (sh + 0)) & 1u)) * scale2 + shift2;
    o.y = (xv.y + (float)((wbits >> (sh + 1)) & 1u)) * scale2 + shift2;
    o.z = (xv.z + (float)((wbits >> (sh + 2)) & 1u)) * scale2 + shift2;
    o.w = (xv.w + (float)((wbits >> (sh + 3)) & 1u)) * scale2 + shift2;
    __stcs(reinterpret_cast<float4*>(out) + i4, o);   // streaming: evict-first
}

// ---------------------------------------------------------------------------
extern "C" void kernel_launch(void* const* d_in, const int* in_sizes, int n_in,
                              void* d_out, int out_size) {
    const float* x  = (const float*)d_in[0];
    const float* cw = (const float*)d_in[1];
    const float* cb = (const float*)d_in[2];
    const float* g1 = (const float*)d_in[3];
    const float* b1 = (const float*)d_in[4];
    const float* g2 = (const float*)d_in[5];
    const float* b2 = (const float*)d_in[6];
    float* out = (float*)d_out;

    k_conv_stats<<<(TB * CC) / 32, 256>>>(x, cw, cb);    // 1024 blocks, asc
    k_lif<<<(BB * CC) / 16, 128>>>(x, cw, cb, g1, b1);   // 512 blocks, DESC
    k_bn2<<<TB * CC, 256>>>(x, g2, b2, out);             // 32768 blocks, asc
}

// round 15
// speedup vs baseline: 1.0308x; 1.0111x over previous
#include <cuda_runtime.h>

// Fixed shapes from reference setup_inputs
#define TT 4
#define BB 32
#define CC 256
#define HW 1024               // 32x32 plane
#define TB 128                // TT*BB
#define NSTAT 131072.0        // TB*HW
#define EPSV 1e-5
#define TSTRIDE (BB*CC*HW)    // element stride between timesteps

// Per-channel stat accumulators (double) + packed spike bits (4 MB).
// g_spk layout (producer K3 / consumer K4):
//   word = plane*32 + cg*4 + k   (plane=(t*BB+b)*CC+c, cg=col>>2, k=row>>3)
//   bit  = (row&7)*4 + j         (j = col&3)
__device__ double g_sum1[CC], g_sumsq1[CC], g_sum2[CC], g_sumsq2[CC];
__device__ unsigned g_spk[(TT * BB * CC * HW) / 32];

// Horizontal 3-tap conv on a float4 strip with scalar edge neighbors.
__device__ __forceinline__ float4 hconv(float w0, float w1, float w2,
                                        float l, float4 v, float r) {
    float4 o;
    o.x = fmaf(w0, l,   fmaf(w1, v.x, w2 * v.y));
    o.y = fmaf(w0, v.x, fmaf(w1, v.y, w2 * v.z));
    o.z = fmaf(w0, v.y, fmaf(w1, v.z, w2 * v.w));
    o.w = fmaf(w0, v.z, fmaf(w1, v.w, w2 * r));
    return o;
}

// Same, with an additive base folded into the innermost op (MUL -> FMA):
// removes the separate "+ base" add per pixel downstream.
__device__ __forceinline__ float4 hconv_b(float w0, float w1, float w2,
                                          float l, float4 v, float r, float base) {
    float4 o;
    o.x = fmaf(w0, l,   fmaf(w1, v.x, fmaf(w2, v.y, base)));
    o.y = fmaf(w0, v.x, fmaf(w1, v.y, fmaf(w2, v.z, base)));
    o.z = fmaf(w0, v.y, fmaf(w1, v.z, fmaf(w2, v.w, base)));
    o.w = fmaf(w0, v.z, fmaf(w1, v.w, fmaf(w2, r,   base)));
    return o;
}

// ---------------------------------------------------------------------------
// K1: depthwise 3x3 conv + bias, per-channel sum/sumsq (BN1 stats).
// Warp = 4 planes, ASCENDING plane order (leaves the tail of x hot in L2 for
// K3's descending pass). Bias folded into the d-hconv (saves 1 FMA-op/px).
// ---------------------------------------------------------------------------
__global__ void __launch_bounds__(256) k_conv_stats(
    const float* __restrict__ x, const float* __restrict__ cw,
    const float* __restrict__ cb)
{
    const int lane = threadIdx.x & 31, warp = threadIdx.x >> 5;
    const int cg = lane & 7;                        // column group
    const int plane = blockIdx.x * 32 + warp * 4 + (lane >> 3);
    const int c = plane & (CC - 1);
    const float* xp = x + (size_t)plane * HW + cg * 4;

    if (blockIdx.x == 0) {  // zero BN2 stats (K1 never reads them)
        g_sum2[threadIdx.x] = 0.0; g_sumsq2[threadIdx.x] = 0.0;
    }

    float w[9];
    #pragma unroll
    for (int i = 0; i < 9; i++) w[i] = __ldg(&cw[c * 9 + i]);
    const float bias = __ldg(&cb[c]);

    float4 acc0 = {0,0,0,0}, acc1 = {0,0,0,0};
    float s = 0.f, ss = 0.f;

    #pragma unroll 8
    for (int r = 0; r < 32; r++) {
        const float4 v = __ldg(reinterpret_cast<const float4*>(xp + r * 32));
        float hl = __shfl_up_sync(0xffffffffu, v.w, 1);   if (cg == 0) hl = 0.f;
        float hr = __shfl_down_sync(0xffffffffu, v.x, 1); if (cg == 7) hr = 0.f;
        float4 a = hconv(w[0], w[1], w[2], hl, v, hr);
        float4 m = hconv(w[3], w[4], w[5], hl, v, hr);
        float4 d = hconv_b(w[6], w[7], w[8], hl, v, hr, bias);  // bias folded
        if (r) {  // output row r-1 complete: y = acc0 + d (d carries bias)
            float yx = acc0.x + d.x, yy = acc0.y + d.y;
            float yz = acc0.z + d.z, yw = acc0.w + d.w;
            s += (yx + yy) + (yz + yw);
            ss = fmaf(yx, yx, fmaf(yy, yy, fmaf(yz, yz, fmaf(yw, yw, ss))));
        }
        acc0.x = acc1.x + m.x; acc0.y = acc1.y + m.y;
        acc0.z = acc1.z + m.z; acc0.w = acc1.w + m.w;
        acc1 = a;
    }
    {   // output row 31 (bottom halo = 0): d-row contribution is just bias
        float yx = acc0.x + bias, yy = acc0.y + bias;
        float yz = acc0.z + bias, yw = acc0.w + bias;
        s += (yx + yy) + (yz + yw);
        ss = fmaf(yx, yx, fmaf(yy, yy, fmaf(yz, yz, fmaf(yw, yw, ss))));
    }
    #pragma unroll
    for (int o = 4; o > 0; o >>= 1) {  // reduce within 8-lane plane group
        s  += __shfl_xor_sync(0xffffffffu, s, o);
        ss += __shfl_xor_sync(0xffffffffu, ss, o);
    }
    if (cg == 0) {
        atomicAdd(&g_sum1[c], (double)s);
        atomicAdd(&g_sumsq1[c], (double)ss);
    }
}

// ---------------------------------------------------------------------------
// K3: fused conv+LIF, warp = 4 planes, 1-row prefetch, DESCENDING plane order
// (L2 chaining with K1). BN1 folding: 0.5*scale1 into weights; 0.5*shift1
// (shift_h) folded into the d-hconv base, so h = fmaf(vm, 0.5, acc0 + d)
// — saves 1 FMA-op per px per timestep vs R14.
// ---------------------------------------------------------------------------
__global__ void __launch_bounds__(128) k_lif(
    const float* __restrict__ x, const float* __restrict__ cw,
    const float* __restrict__ cb, const float* __restrict__ g1,
    const float* __restrict__ b1)
{
    const int lane = threadIdx.x & 31, warp = threadIdx.x >> 5;
    const int cg = lane & 7;
    const int rbid = (int)gridDim.x - 1 - (int)blockIdx.x;      // reversed
    const int plane = rbid * 16 + warp * 4 + (lane >> 3);       // b*CC + c
    const int c = plane & (CC - 1);
    const float* xp = x + (size_t)plane * HW + cg * 4;

    const double mu  = g_sum1[c] * (1.0 / NSTAT);
    const double var = g_sumsq1[c] * (1.0 / NSTAT) - mu * mu;
    const float scale1 = __ldg(&g1[c]) * (float)rsqrt(var + EPSV);
    const float shift_h = 0.5f * (__ldg(&b1[c]) + (__ldg(&cb[c]) - (float)mu) * scale1);
    const float ws = 0.5f * scale1;
    float w[9];
    #pragma unroll
    for (int i = 0; i < 9; i++) w[i] = __ldg(&cw[c * 9 + i]) * ws;

    float4 acc0[TT], acc1[TT], vprev[TT], vbuf[TT];
    unsigned spw[TT];
    #pragma unroll
    for (int t = 0; t < TT; t++) {
        acc0[t] = make_float4(0,0,0,0); acc1[t] = make_float4(0,0,0,0);
        vprev[t] = make_float4(0,0,0,0); spw[t] = 0u;
        vbuf[t] = __ldg(reinterpret_cast<const float4*>(
                        xp + (size_t)t * TSTRIDE));   // preload row 0
    }
    float s2 = 0.f, ss2 = 0.f;

    #pragma unroll 2
    for (int r = 0; r < 32; r++) {
        // ---- prefetch row r+1 first (row 31 reloads itself: L1 hit) ----
        float4 vnext[TT];
        const int rn = (r < 31) ? r + 1 : 31;
        #pragma unroll
        for (int t = 0; t < TT; t++)
            vnext[t] = __ldg(reinterpret_cast<const float4*>(
                             xp + (size_t)t * TSTRIDE + rn * 32));

        const bool out_valid = (r >= 1);
        const int sh = ((r - 1) & 7) * 4;        // nibble shift for output row
        float4 vm = make_float4(0,0,0,0);        // membrane, chains over t
        #pragma unroll
        for (int t = 0; t < TT; t++) {
            const float4 v = vbuf[t];
            float hl = __shfl_up_sync(0xffffffffu, v.w, 1);   if (cg == 0) hl = 0.f;
            float hr = __shfl_down_sync(0xffffffffu, v.x, 1); if (cg == 7) hr = 0.f;
            float4 a = hconv(w[0], w[1], w[2], hl, v, hr);
            float4 m = hconv(w[3], w[4], w[5], hl, v, hr);
            float4 d = hconv_b(w[6], w[7], w[8], hl, v, hr, shift_h);  // folded
            if (out_valid) {   // output row r-1 for timestep t
                float hx = fmaf(vm.x, 0.5f, acc0[t].x + d.x);
                float hy = fmaf(vm.y, 0.5f, acc0[t].y + d.y);
                float hz = fmaf(vm.z, 0.5f, acc0[t].z + d.z);
                float hw = fmaf(vm.w, 0.5f, acc0[t].w + d.w);
                bool f0 = hx >= 1.f, f1 = hy >= 1.f, f2 = hz >= 1.f, f3 = hw >= 1.f;
                vm.x = f0 ? 0.f : hx; vm.y = f1 ? 0.f : hy;
                vm.z = f2 ? 0.f : hz; vm.w = f3 ? 0.f : hw;
                unsigned nib = (f0 ? 1u : 0u) | (f1 ? 2u : 0u)
                             | (f2 ? 4u : 0u) | (f3 ? 8u : 0u);
                spw[t] |= nib << sh;
                float zx = (f0 ? 1.f : 0.f) + vprev[t].x;
                float zy = (f1 ? 1.f : 0.f) + vprev[t].y;
                float zz = (f2 ? 1.f : 0.f) + vprev[t].z;
                float zw = (f3 ? 1.f : 0.f) + vprev[t].w;
                s2 += (zx + zy) + (zz + zw);
                ss2 = fmaf(zx, zx, fmaf(zy, zy, fmaf(zz, zz, fmaf(zw, zw, ss2))));
            }
            acc0[t].x = acc1[t].x + m.x; acc0[t].y = acc1[t].y + m.y;
            acc0[t].z = acc1[t].z + m.z; acc0[t].w = acc1[t].w + m.w;
            acc1[t] = a;
            vprev[t] = v;
            vbuf[t] = vnext[t];
        }
        if (out_valid && (((r - 1) & 7) == 7)) {  // flush rows (r-1 = 7,15,23)
            const int k = (r - 1) >> 3;
            #pragma unroll
            for (int t = 0; t < TT; t++) {
                g_spk[((size_t)(t * BB * CC) + plane) * 32 + cg * 4 + k] = spw[t];
                spw[t] = 0u;
            }
        }
    }
    {   // output row 31 (bottom halo = 0): d-row contribution is just shift_h
        float4 vm = make_float4(0,0,0,0);
        #pragma unroll
        for (int t = 0; t < TT; t++) {
            float hx = fmaf(vm.x, 0.5f, acc0[t].x + shift_h);
            float hy = fmaf(vm.y, 0.5f, acc0[t].y + shift_h);
            float hz = fmaf(vm.z, 0.5f, acc0[t].z + shift_h);
            float hw = fmaf(vm.w, 0.5f, acc0[t].w + shift_h);
            bool f0 = hx >= 1.f, f1 = hy >= 1.f, f2 = hz >= 1.f, f3 = hw >= 1.f;
            vm.x = f0 ? 0.f : hx; vm.y = f1 ? 0.f : hy;
            vm.z = f2 ? 0.f : hz; vm.w = f3 ? 0.f : hw;
            unsigned nib = (f0 ? 1u : 0u) | (f1 ? 2u : 0u)
                         | (f2 ? 4u : 0u) | (f3 ? 8u : 0u);
            spw[t] |= nib << 28;  // (31&7)*4
            float zx = (f0 ? 1.f : 0.f) + vprev[t].x;
            float zy = (f1 ? 1.f : 0.f) + vprev[t].y;
            float zz = (f2 ? 1.f : 0.f) + vprev[t].z;
            float zw = (f3 ? 1.f : 0.f) + vprev[t].w;
            s2 += (zx + zy) + (zz + zw);
            ss2 = fmaf(zx, zx, fmaf(zy, zy, fmaf(zz, zz, fmaf(zw, zw, ss2))));
            g_spk[((size_t)(t * BB * CC) + plane) * 32 + cg * 4 + 3] = spw[t];
        }
    }
    #pragma unroll
    for (int o = 4; o > 0; o >>= 1) {  // reduce within 8-lane plane group
        s2  += __shfl_xor_sync(0xffffffffu, s2, o);
        ss2 += __shfl_xor_sync(0xffffffffu, ss2, o);
    }
    if (cg == 0) {
        atomicAdd(&g_sum2[c], (double)s2);
        atomicAdd(&g_sumsq2[c], (double)ss2);
    }
}

// ---------------------------------------------------------------------------
// K4: out = BN2(spike + x), ascending order (picks up K3-descending's L2 tail).
// Streaming stores (__stcs) keep x's L2 lines resident. One block = one plane.
// Block 0 zeros BN1 stats for the next launch.
// ---------------------------------------------------------------------------
__global__ void __launch_bounds__(256) k_bn2(
    const float* __restrict__ x, const float* __restrict__ g2,
    const float* __restrict__ b2, float* __restrict__ out)
{
    __shared__ float s_scale, s_shift;
    const int c = blockIdx.x & (CC - 1);

    if (threadIdx.x == 0) {
        double m   = g_sum2[c] * (1.0 / NSTAT);
        double var = g_sumsq2[c] * (1.0 / NSTAT) - m * m;
        float  sc  = __ldg(&g2[c]) * (float)rsqrt(var + EPSV);
        s_scale = sc;
        s_shift = __ldg(&b2[c]) - (float)m * sc;
    }
    if (blockIdx.x == 0) {  // reset BN1 stats for next launch
        g_sum1[threadIdx.x] = 0.0; g_sumsq1[threadIdx.x] = 0.0;
    }
    __syncthreads();
    const float scale2 = s_scale, shift2 = s_shift;

    const unsigned i4 = blockIdx.x * 256u + threadIdx.x;  // float4 index
    const float4 xv = reinterpret_cast<const float4*>(x)[i4];

    // word = plane*32 + cg*4 + k ; plane=i4>>8, cg=i4&7, k=(i4>>6)&3
    const unsigned widx = (i4 >> 8) * 32u + (i4 & 7u) * 4u + ((i4 >> 6) & 3u);
    const unsigned wbits = g_spk[widx];
    const int sh = (int)((i4 >> 1) & 0x1Cu);  // ((row&7)*4)

    float4 o;
    o.x = (xv.x + (float)((wbits >> (sh + 0)) & 1u)) * scale2 + shift2;
    o.y = (xv.y + (float)((wbits >> (sh + 1)) & 1u)) * scale2 + shift2;
    o.z = (xv.z + (float)((wbits >> (sh + 2)) & 1u)) * scale2 + shift2;
    o.w = (xv.w + (float)((wbits >> (sh + 3)) & 1u)) * scale2 + shift2;
    __stcs(reinterpret_cast<float4*>(out) + i4, o);   // streaming: evict-first
}

// ---------------------------------------------------------------------------
extern "C" void kernel_launch(void* const* d_in, const int* in_sizes, int n_in,
                              void* d_out, int out_size) {
    const float* x  = (const float*)d_in[0];
    const float* cw = (const float*)d_in[1];
    const float* cb = (const float*)d_in[2];
    const float* g1 = (const float*)d_in[3];
    const float* b1 = (const float*)d_in[4];
    const float* g2 = (const float*)d_in[5];
    const float* b2 = (const float*)d_in[6];
    float* out = (float*)d_out;

    k_conv_stats<<<(TB * CC) / 32, 256>>>(x, cw, cb);    // 1024 blocks, asc
    k_lif<<<(BB * CC) / 16, 128>>>(x, cw, cb, g1, b1);   // 512 blocks, DESC
    k_bn2<<<TB * CC, 256>>>(x, g2, b2, out);             // 32768 blocks, asc
}

// round 16
// speedup vs baseline: 1.0501x; 1.0187x over previous
#include <cuda_runtime.h>

// Fixed shapes from reference setup_inputs
#define TT 4
#define BB 32
#define CC 256
#define HW 1024               // 32x32 plane
#define TB 128                // TT*BB
#define NSTAT 131072.0        // TB*HW
#define EPSV 1e-5
#define TSTRIDE (BB*CC*HW)    // element stride between timesteps

// Per-channel stat accumulators (double) + packed spike bits (4 MB).
// g_spk layout (producer K3 / consumer K4):
//   word = plane*32 + cg*4 + k   (plane=(t*BB+b)*CC+c, cg=col>>2, k=row>>3)
//   bit  = (row&7)*4 + j         (j = col&3)
__device__ double g_sum1[CC], g_sumsq1[CC], g_sum2[CC], g_sumsq2[CC];
__device__ unsigned g_spk[(TT * BB * CC * HW) / 32];

// cp.async helpers (16B, L1-bypass .cg — we want the L2 path from K1 chaining)
#define CP16(dst_u32, src_ptr) \
    asm volatile("cp.async.cg.shared.global [%0], [%1], 16;" \
                 :: "r"(dst_u32), "l"(src_ptr) : "memory")
#define CP_COMMIT() asm volatile("cp.async.commit_group;" ::: "memory")
#define CP_WAIT2()  asm volatile("cp.async.wait_group 2;"  ::: "memory")

// Horizontal 3-tap conv on a float4 strip with scalar edge neighbors.
__device__ __forceinline__ float4 hconv(float w0, float w1, float w2,
                                        float l, float4 v, float r) {
    float4 o;
    o.x = fmaf(w0, l,   fmaf(w1, v.x, w2 * v.y));
    o.y = fmaf(w0, v.x, fmaf(w1, v.y, w2 * v.z));
    o.z = fmaf(w0, v.y, fmaf(w1, v.z, w2 * v.w));
    o.w = fmaf(w0, v.z, fmaf(w1, v.w, w2 * r));
    return o;
}

// Same, with an additive base folded into the innermost op (MUL -> FMA).
__device__ __forceinline__ float4 hconv_b(float w0, float w1, float w2,
                                          float l, float4 v, float r, float base) {
    float4 o;
    o.x = fmaf(w0, l,   fmaf(w1, v.x, fmaf(w2, v.y, base)));
    o.y = fmaf(w0, v.x, fmaf(w1, v.y, fmaf(w2, v.z, base)));
    o.z = fmaf(w0, v.y, fmaf(w1, v.z, fmaf(w2, v.w, base)));
    o.w = fmaf(w0, v.z, fmaf(w1, v.w, fmaf(w2, r,   base)));
    return o;
}

// ---------------------------------------------------------------------------
// K1: depthwise 3x3 conv + bias, per-channel sum/sumsq (BN1 stats).
// Warp = 4 planes, ascending plane order. Bias folded into d-hconv.
// At its FMA-pipe floor (~29 us). Unchanged from R15 best.
// ---------------------------------------------------------------------------
__global__ void __launch_bounds__(256) k_conv_stats(
    const float* __restrict__ x, const float* __restrict__ cw,
    const float* __restrict__ cb)
{
    const int lane = threadIdx.x & 31, warp = threadIdx.x >> 5;
    const int cg = lane & 7;                        // column group
    const int plane = blockIdx.x * 32 + warp * 4 + (lane >> 3);
    const int c = plane & (CC - 1);
    const float* xp = x + (size_t)plane * HW + cg * 4;

    if (blockIdx.x == 0) {  // zero BN2 stats (K1 never reads them)
        g_sum2[threadIdx.x] = 0.0; g_sumsq2[threadIdx.x] = 0.0;
    }

    float w[9];
    #pragma unroll
    for (int i = 0; i < 9; i++) w[i] = __ldg(&cw[c * 9 + i]);
    const float bias = __ldg(&cb[c]);

    float4 acc0 = {0,0,0,0}, acc1 = {0,0,0,0};
    float s = 0.f, ss = 0.f;

    #pragma unroll 8
    for (int r = 0; r < 32; r++) {
        const float4 v = __ldg(reinterpret_cast<const float4*>(xp + r * 32));
        float hl = __shfl_up_sync(0xffffffffu, v.w, 1);   if (cg == 0) hl = 0.f;
        float hr = __shfl_down_sync(0xffffffffu, v.x, 1); if (cg == 7) hr = 0.f;
        float4 a = hconv(w[0], w[1], w[2], hl, v, hr);
        float4 m = hconv(w[3], w[4], w[5], hl, v, hr);
        float4 d = hconv_b(w[6], w[7], w[8], hl, v, hr, bias);  // bias folded
        if (r) {  // output row r-1 complete: y = acc0 + d (d carries bias)
            float yx = acc0.x + d.x, yy = acc0.y + d.y;
            float yz = acc0.z + d.z, yw = acc0.w + d.w;
            s += (yx + yy) + (yz + yw);
            ss = fmaf(yx, yx, fmaf(yy, yy, fmaf(yz, yz, fmaf(yw, yw, ss))));
        }
        acc0.x = acc1.x + m.x; acc0.y = acc1.y + m.y;
        acc0.z = acc1.z + m.z; acc0.w = acc1.w + m.w;
        acc1 = a;
    }
    {   // output row 31 (bottom halo = 0)
        float yx = acc0.x + bias, yy = acc0.y + bias;
        float yz = acc0.z + bias, yw = acc0.w + bias;
        s += (yx + yy) + (yz + yw);
        ss = fmaf(yx, yx, fmaf(yy, yy, fmaf(yz, yz, fmaf(yw, yw, ss))));
    }
    #pragma unroll
    for (int o = 4; o > 0; o >>= 1) {  // reduce within 8-lane plane group
        s  += __shfl_xor_sync(0xffffffffu, s, o);
        ss += __shfl_xor_sync(0xffffffffu, ss, o);
    }
    if (cg == 0) {
        atomicAdd(&g_sum1[c], (double)s);
        atomicAdd(&g_sumsq1[c], (double)ss);
    }
}

// ---------------------------------------------------------------------------
// K3: fused conv+LIF, warp = 4 planes, DESCENDING plane order (L2 chaining),
// BN1 folded into weights. NEW: 3-STAGE cp.async RING — rows r+1 and r+2 are
// in flight (wait_group 2) at ZERO register cost; each lane reads back its own
// 16B slot (no syncs, conflict-free LDS.128). Frees vbuf/vnext registers.
// ---------------------------------------------------------------------------
__global__ void __launch_bounds__(128) k_lif(
    const float* __restrict__ x, const float* __restrict__ cw,
    const float* __restrict__ cb, const float* __restrict__ g1,
    const float* __restrict__ b1)
{
    __shared__ float4 sbuf[3][4][TT][32];   // [stage][warp][t][lane] = 24 KB

    const int lane = threadIdx.x & 31, warp = threadIdx.x >> 5;
    const int cg = lane & 7;
    const int rbid = (int)gridDim.x - 1 - (int)blockIdx.x;      // reversed
    const int plane = rbid * 16 + warp * 4 + (lane >> 3);       // b*CC + c
    const int c = plane & (CC - 1);
    const float* xp = x + (size_t)plane * HW + cg * 4;

    // shared-space base address of this thread's slots
    unsigned sb[3];
    #pragma unroll
    for (int s = 0; s < 3; s++)
        sb[s] = (unsigned)__cvta_generic_to_shared(&sbuf[s][warp][0][lane]);
    const unsigned tstep = (unsigned)(32 * sizeof(float4));     // t stride in sbuf

    const double mu  = g_sum1[c] * (1.0 / NSTAT);
    const double var = g_sumsq1[c] * (1.0 / NSTAT) - mu * mu;
    const float scale1 = __ldg(&g1[c]) * (float)rsqrt(var + EPSV);
    const float shift_h = 0.5f * (__ldg(&b1[c]) + (__ldg(&cb[c]) - (float)mu) * scale1);
    const float ws = 0.5f * scale1;
    float w[9];
    #pragma unroll
    for (int i = 0; i < 9; i++) w[i] = __ldg(&cw[c * 9 + i]) * ws;

    float4 acc0[TT], acc1[TT], vprev[TT];
    unsigned spw[TT];
    #pragma unroll
    for (int t = 0; t < TT; t++) {
        acc0[t] = make_float4(0,0,0,0); acc1[t] = make_float4(0,0,0,0);
        vprev[t] = make_float4(0,0,0,0); spw[t] = 0u;
    }

    // Prologue: rows 0 and 1 into stages 0 and 1 (two commit groups)
    #pragma unroll
    for (int s = 0; s < 2; s++) {
        #pragma unroll
        for (int t = 0; t < TT; t++)
            CP16(sb[s] + t * tstep, xp + (size_t)t * TSTRIDE + s * 32);
        CP_COMMIT();
    }

    float s2 = 0.f, ss2 = 0.f;
    int st_use = 0, st_load = 2;

    for (int r = 0; r < 32; r++) {
        // issue row r+2 into st_load (empty group at the tail keeps counts uniform)
        if (r < 30) {
            #pragma unroll
            for (int t = 0; t < TT; t++)
                CP16(sb[st_load] + t * tstep, xp + (size_t)t * TSTRIDE + (r + 2) * 32);
        }
        CP_COMMIT();
        CP_WAIT2();   // all groups up to row r complete

        const bool out_valid = (r >= 1);
        const int sh = ((r - 1) & 7) * 4;        // nibble shift for output row
        float4 vm = make_float4(0,0,0,0);        // membrane, chains over t
        #pragma unroll
        for (int t = 0; t < TT; t++) {
            const float4 v = sbuf[st_use][warp][t][lane];
            float hl = __shfl_up_sync(0xffffffffu, v.w, 1);   if (cg == 0) hl = 0.f;
            float hr = __shfl_down_sync(0xffffffffu, v.x, 1); if (cg == 7) hr = 0.f;
            float4 a = hconv(w[0], w[1], w[2], hl, v, hr);
            float4 m = hconv(w[3], w[4], w[5], hl, v, hr);
            float4 d = hconv_b(w[6], w[7], w[8], hl, v, hr, shift_h);  // folded
            if (out_valid) {   // output row r-1 for timestep t
                float hx = fmaf(vm.x, 0.5f, acc0[t].x + d.x);
                float hy = fmaf(vm.y, 0.5f, acc0[t].y + d.y);
                float hz = fmaf(vm.z, 0.5f, acc0[t].z + d.z);
                float hw = fmaf(vm.w, 0.5f, acc0[t].w + d.w);
                bool f0 = hx >= 1.f, f1 = hy >= 1.f, f2 = hz >= 1.f, f3 = hw >= 1.f;
                vm.x = f0 ? 0.f : hx; vm.y = f1 ? 0.f : hy;
                vm.z = f2 ? 0.f : hz; vm.w = f3 ? 0.f : hw;
                unsigned nib = (f0 ? 1u : 0u) | (f1 ? 2u : 0u)
                             | (f2 ? 4u : 0u) | (f3 ? 8u : 0u);
                spw[t] |= nib << sh;
                float zx = (f0 ? 1.f : 0.f) + vprev[t].x;
                float zy = (f1 ? 1.f : 0.f) + vprev[t].y;
                float zz = (f2 ? 1.f : 0.f) + vprev[t].z;
                float zw = (f3 ? 1.f : 0.f) + vprev[t].w;
                s2 += (zx + zy) + (zz + zw);
                ss2 = fmaf(zx, zx, fmaf(zy, zy, fmaf(zz, zz, fmaf(zw, zw, ss2))));
            }
            acc0[t].x = acc1[t].x + m.x; acc0[t].y = acc1[t].y + m.y;
            acc0[t].z = acc1[t].z + m.z; acc0[t].w = acc1[t].w + m.w;
            acc1[t] = a;
            vprev[t] = v;
        }
        if (out_valid && (((r - 1) & 7) == 7)) {  // flush rows (r-1 = 7,15,23)
            const int k = (r - 1) >> 3;
            #pragma unroll
            for (int t = 0; t < TT; t++) {
                g_spk[((size_t)(t * BB * CC) + plane) * 32 + cg * 4 + k] = spw[t];
                spw[t] = 0u;
            }
        }
        st_use  = (st_use  == 2) ? 0 : st_use + 1;
        st_load = (st_load == 2) ? 0 : st_load + 1;
    }
    {   // output row 31 (bottom halo = 0): d-row contribution is just shift_h
        float4 vm = make_float4(0,0,0,0);
        #pragma unroll
        for (int t = 0; t < TT; t++) {
            float hx = fmaf(vm.x, 0.5f, acc0[t].x + shift_h);
            float hy = fmaf(vm.y, 0.5f, acc0[t].y + shift_h);
            float hz = fmaf(vm.z, 0.5f, acc0[t].z + shift_h);
            float hw = fmaf(vm.w, 0.5f, acc0[t].w + shift_h);
            bool f0 = hx >= 1.f, f1 = hy >= 1.f, f2 = hz >= 1.f, f3 = hw >= 1.f;
            vm.x = f0 ? 0.f : hx; vm.y = f1 ? 0.f : hy;
            vm.z = f2 ? 0.f : hz; vm.w = f3 ? 0.f : hw;
            unsigned nib = (f0 ? 1u : 0u) | (f1 ? 2u : 0u)
                         | (f2 ? 4u : 0u) | (f3 ? 8u : 0u);
            spw[t] |= nib << 28;  // (31&7)*4
            float zx = (f0 ? 1.f : 0.f) + vprev[t].x;
            float zy = (f1 ? 1.f : 0.f) + vprev[t].y;
            float zz = (f2 ? 1.f : 0.f) + vprev[t].z;
            float zw = (f3 ? 1.f : 0.f) + vprev[t].w;
            s2 += (zx + zy) + (zz + zw);
            ss2 = fmaf(zx, zx, fmaf(zy, zy, fmaf(zz, zz, fmaf(zw, zw, ss2))));
            g_spk[((size_t)(t * BB * CC) + plane) * 32 + cg * 4 + 3] = spw[t];
        }
    }
    #pragma unroll
    for (int o = 4; o > 0; o >>= 1) {  // reduce within 8-lane plane group
        s2  += __shfl_xor_sync(0xffffffffu, s2, o);
        ss2 += __shfl_xor_sync(0xffffffffu, ss2, o);
    }
    if (cg == 0) {
        atomicAdd(&g_sum2[c], (double)s2);
        atomicAdd(&g_sumsq2[c], (double)ss2);
    }
}

// ---------------------------------------------------------------------------
// K4: out = BN2(spike + x), ascending order (picks up K3-descending's L2 tail).
// Streaming stores (__stcs). One block = one plane. Block 0 zeros BN1 stats.
// ---------------------------------------------------------------------------
__global__ void __launch_bounds__(256) k_bn2(
    const float* __restrict__ x, const float* __restrict__ g2,
    const float* __restrict__ b2, float* __restrict__ out)
{
    __shared__ float s_scale, s_shift;
    const int c = blockIdx.x & (CC - 1);

    if (threadIdx.x == 0) {
        double m   = g_sum2[c] * (1.0 / NSTAT);
        double var = g_sumsq2[c] * (1.0 / NSTAT) - m * m;
        float  sc  = __ldg(&g2[c]) * (float)rsqrt(var + EPSV);
        s_scale = sc;
        s_shift = __ldg(&b2[c]) - (float)m * sc;
    }
    if (blockIdx.x == 0) {  // reset BN1 stats for next launch
        g_sum1[threadIdx.x] = 0.0; g_sumsq1[threadIdx.x] = 0.0;
    }
    __syncthreads();
    const float scale2 = s_scale, shift2 = s_shift;

    const unsigned i4 = blockIdx.x * 256u + threadIdx.x;  // float4 index
    const float4 xv = reinterpret_cast<const float4*>(x)[i4];

    // word = plane*32 + cg*4 + k ; plane=i4>>8, cg=i4&7, k=(i4>>6)&3
    const unsigned widx = (i4 >> 8) * 32u + (i4 & 7u) * 4u + ((i4 >> 6) & 3u);
    const unsigned wbits = g_spk[widx];
    const int sh = (int)((i4 >> 1) & 0x1Cu);  // ((row&7)*4)

    float4 o;
    o.x = (xv.x + (float)((wbits >> (sh + 0)) & 1u)) * scale2 + shift2;
    o.y = (xv.y + (float)((wbits >> (sh + 1)) & 1u)) * scale2 + shift2;
    o.z = (xv.z + (float)((wbits >> (sh + 2)) & 1u)) * scale2 + shift2;
    o.w = (xv.w + (float)((wbits >> (sh + 3)) & 1u)) * scale2 + shift2;
    __stcs(reinterpret_cast<float4*>(out) + i4, o);   // streaming: evict-first
}

// ---------------------------------------------------------------------------
extern "C" void kernel_launch(void* const* d_in, const int* in_sizes, int n_in,
                              void* d_out, int out_size) {
    const float* x  = (const float*)d_in[0];
    const float* cw = (const float*)d_in[1];
    const float* cb = (const float*)d_in[2];
    const float* g1 = (const float*)d_in[3];
    const float* b1 = (const float*)d_in[4];
    const float* g2 = (const float*)d_in[5];
    const float* b2 = (const float*)d_in[6];
    float* out = (float*)d_out;

    k_conv_stats<<<(TB * CC) / 32, 256>>>(x, cw, cb);    // 1024 blocks, asc
    k_lif<<<(BB * CC) / 16, 128>>>(x, cw, cb, g1, b1);   // 512 blocks, DESC
    k_bn2<<<TB * CC, 256>>>(x, g2, b2, out);             // 32768 blocks, asc
}